// round 7
// baseline (speedup 1.0000x reference)
#include <cuda_runtime.h>
#include <math.h>

#define BB 32
#define TT 1024
#define DD 512
#define HH 512

// ---------------- scratch (device globals: allocation-free) ----------------
__device__ float g_pre[TT * BB * HH];   // layer-0 input transform + bias, [t][b][j]
__device__ float g_h0[2][BB][HH];       // layer-0 hidden double buffer
__device__ float g_h1[2][BB][HH];       // layer-1 hidden double buffer

// ---------------- helpers ----------------------------------------------------
__device__ __forceinline__ void fma2(unsigned long long& d,
                                     unsigned long long a, unsigned long long b) {
    asm("fma.rn.f32x2 %0, %1, %2, %0;" : "+l"(d) : "l"(a), "l"(b));
}
__device__ __forceinline__ unsigned long long addf2(unsigned long long a,
                                                    unsigned long long b) {
    unsigned long long d;
    asm("add.rn.f32x2 %0, %1, %2;" : "=l"(d) : "l"(a), "l"(b));
    return d;
}

// ---------------- init: zero recurrent state ---------------------------------
__global__ void init_state() {
    int idx = blockIdx.x * blockDim.x + threadIdx.x;
    if (idx < 2 * BB * HH) {
        ((float*)g_h0)[idx] = 0.f;
        ((float*)g_h1)[idx] = 0.f;
    }
}

// ---------------- pre-GEMM (layer 0 only): pre[t*B+b][j] = x_row.W[j]+bias --
__global__ __launch_bounds__(256) void gemm_pre(
    const float* __restrict__ X, const float* __restrict__ W,
    const float* __restrict__ b1, const float* __restrict__ b2)
{
    __shared__ float As[16][68];
    __shared__ float Bs[16][68];

    const int m0 = blockIdx.y * 64;
    const int n0 = blockIdx.x * 64;
    const int tid = threadIdx.x;
    const int r  = tid >> 2;
    const int kq = tid & 3;
    const int tx = tid & 15;
    const int ty = tid >> 4;

    const int m = m0 + r;
    const int t = m >> 5, b = m & 31;
    const float* arow = X + ((size_t)b * TT + t) * DD;
    const float* brow = W + (size_t)(n0 + r) * DD;

    float acc[4][4];
#pragma unroll
    for (int i = 0; i < 4; i++)
#pragma unroll
        for (int j = 0; j < 4; j++) acc[i][j] = 0.f;

    float4 a_next = *(const float4*)(arow + kq * 4);
    float4 b_next = *(const float4*)(brow + kq * 4);

    for (int kt = 0; kt < DD / 16; kt++) {
        float4 a = a_next, bv = b_next;
        As[kq*4+0][r] = a.x;  As[kq*4+1][r] = a.y;
        As[kq*4+2][r] = a.z;  As[kq*4+3][r] = a.w;
        Bs[kq*4+0][r] = bv.x; Bs[kq*4+1][r] = bv.y;
        Bs[kq*4+2][r] = bv.z; Bs[kq*4+3][r] = bv.w;
        __syncthreads();
        if (kt + 1 < DD / 16) {
            a_next = *(const float4*)(arow + (kt + 1) * 16 + kq * 4);
            b_next = *(const float4*)(brow + (kt + 1) * 16 + kq * 4);
        }
#pragma unroll
        for (int k = 0; k < 16; k++) {
            float4 av = *(const float4*)&As[k][ty * 4];
            float4 bw = *(const float4*)&Bs[k][tx * 4];
            float am[4] = {av.x, av.y, av.z, av.w};
            float bn[4] = {bw.x, bw.y, bw.z, bw.w};
#pragma unroll
            for (int i = 0; i < 4; i++)
#pragma unroll
                for (int j = 0; j < 4; j++) acc[i][j] += am[i] * bn[j];
        }
        __syncthreads();
    }

    float bias[4];
#pragma unroll
    for (int j = 0; j < 4; j++) {
        int n = n0 + tx * 4 + j;
        bias[j] = b1[n] + b2[n];
    }
#pragma unroll
    for (int i = 0; i < 4; i++) {
        int mo = m0 + ty * 4 + i;
        float4 v;
        v.x = acc[i][0] + bias[0];
        v.y = acc[i][1] + bias[1];
        v.z = acc[i][2] + bias[2];
        v.w = acc[i][3] + bias[3];
        *(float4*)&g_pre[(size_t)mo * HH + n0 + tx * 4] = v;
    }
}

// ---------------- clustered fused recurrence ---------------------------------
// 8 independent clusters of 16 CTAs. Cluster c owns batches [4c, 4c+4), both
// layers, all 1024 steps — no inter-cluster sync whatsoever.
// CTA rank owns j-rows [rank*32, rank*32+32) of Whh0, Wih1, Whh1 (96 rows,
// 512 floats each, SMEM pitch 512 with 16B-chunk swizzle phys = c ^ (2*(row&7))).
// Round r: mat0 -> h0[r] (r<TT); mats1+2 -> h1[r-1] (r>=1).
// h exchange via global double buffers, ordered by barrier.cluster (release/acquire).
#define HP 516
#define W_FLOATS (96 * 512)
#define SMEM_CL ((W_FLOATS + 2 * 4 * HP + 3 * 128 * 4 + 32) * 4)

__global__ __launch_bounds__(384, 1) __cluster_dims__(16, 1, 1)
void rnn_cluster(
    const float* __restrict__ Whh0, const float* __restrict__ Wih1,
    const float* __restrict__ Whh1, const float* __restrict__ bih1,
    const float* __restrict__ bhh1, float* __restrict__ out)
{
    extern __shared__ float sm[];
    float* Ws  = sm;                       // 96 x 512 (chunk-swizzled)
    float* Hs0 = sm + W_FLOATS;            // 4 x HP (h0[r-1])
    float* Hs1 = Hs0 + 4 * HP;             // 4 x HP (h1[r-2])
    float* red = Hs1 + 4 * HP;             // [mat][b*32+j][4]
    float* b1s = red + 3 * 128 * 4;        // 32 biases

    const int tid  = threadIdx.x;
    const int wid  = tid >> 5;
    const int lane = tid & 31;
    unsigned rank;
    asm("mov.u32 %0, %%cluster_ctarank;" : "=r"(rank));
    const int cid = blockIdx.x >> 4;       // cluster id 0..7

    // ---- load weight slice with chunk swizzle (once) ----
    for (int i = tid; i < 96 * 128; i += 384) {
        int row = i >> 7, c = i & 127;
        int m = row >> 5, lr = row & 31;
        const float* src = (m == 0) ? Whh0 + (size_t)(rank * 32 + lr) * HH
                         : (m == 1) ? Wih1 + (size_t)(rank * 32 + lr) * HH
                                    : Whh1 + (size_t)(rank * 32 + lr) * HH;
        int phys = c ^ (2 * (row & 7));
        *(float4*)&Ws[row * 512 + phys * 4] = *(const float4*)(src + c * 4);
    }
    if (tid < 32) b1s[tid] = bih1[rank * 32 + tid] + bhh1[rank * 32 + tid];

    // ---- compute-lane decomposition: 3 mats x 4 warps; tile 4j x 4b --------
    const int mat = wid % 3;
    const int wom = wid / 3;               // 0..3
    const int jq    = lane & 7;            // j = jq + 8*jj
    const int kpart = lane >> 3;           // 0..3 ; ks = wom*4 + kpart (16 slices)
    const int ks = wom * 4 + kpart;
    const int ksx = ks ^ (2 * jq);         // swizzled chunk base (both < 16)
    const float* wb = Ws + (mat * 32 + jq) * 512 + ksx * 4;  // jj stride 8*512
    const float* hb = ((mat == 2) ? Hs1 : Hs0) + ks * 4;     // bb stride HP

    // ---- consumer decomposition ----
    const int ct = tid & 127;
    const int cb = ct >> 5;                // batch within cluster (warp-major)
    const int cj = ct & 31;                // local j (lane-major -> coalesced)
    const int gb = cid * 4 + cb;
    const int gj = rank * 32 + cj;
    const size_t HIDOFF = (size_t)BB * TT * HH;

    float pv = (tid < 128) ? g_pre[((size_t)0 * BB + gb) * HH + gj] : 0.f;

    __syncthreads();   // weights/bias ready (stage below also syncs, but be safe)

    for (int r = 0; r <= TT; r++) {
        const int cur = r & 1, nxt = cur ^ 1;

        // ---- stage h0[r-1], h1[r-2] (4 batches x 512) from global ----
        for (int i = tid; i < 512; i += 384) {
            int b = i >> 7, c = i & 127;
            *(float4*)&Hs0[b * HP + c * 4] = *(const float4*)&g_h0[cur][cid * 4 + b][c * 4];
            *(float4*)&Hs1[b * HP + c * 4] = *(const float4*)&g_h1[cur][cid * 4 + b][c * 4];
        }
        __syncthreads();

        // ---- compute: per lane 4j x 4b over its 32-k slice ----
        unsigned long long acc[4][4];
#pragma unroll
        for (int a = 0; a < 4; a++)
#pragma unroll
            for (int b = 0; b < 4; b++) acc[a][b] = 0ull;

#pragma unroll
        for (int i = 0; i < 8; i++) {
            ulonglong2 h[4];
#pragma unroll
            for (int bb = 0; bb < 4; bb++)
                h[bb] = *(const ulonglong2*)(hb + bb * HP + i * 64);
#pragma unroll
            for (int jj = 0; jj < 4; jj++) {
                ulonglong2 w = *(const ulonglong2*)(wb + jj * 4096 + i * 64);
#pragma unroll
                for (int bb = 0; bb < 4; bb++) {
                    fma2(acc[jj][bb], w.x, h[bb].x);
                    fma2(acc[jj][bb], w.y, h[bb].y);
                }
            }
        }

        // ---- butterfly reduce over kpart (lane bits 3,4) ----
#pragma unroll
        for (int jj = 0; jj < 4; jj++)
#pragma unroll
            for (int bb = 0; bb < 4; bb++) {
                unsigned long long v = acc[jj][bb];
                v = addf2(v, __shfl_xor_sync(0xffffffffu, v, 8));
                v = addf2(v, __shfl_xor_sync(0xffffffffu, v, 16));
                acc[jj][bb] = v;
            }
        if (lane < 8) {   // kpart==0 lanes hold complete sums; write all 16
#pragma unroll
            for (int jj = 0; jj < 4; jj++)
#pragma unroll
                for (int bb = 0; bb < 4; bb++) {
                    unsigned long long v = acc[jj][bb];
                    float s = __uint_as_float((unsigned)v)
                            + __uint_as_float((unsigned)(v >> 32));
                    red[(mat * 128 + bb * 32 + jq + 8 * jj) * 4 + wom] = s;
                }
        }
        __syncthreads();

        // ---- consumers ----
        if (tid < 128) {
            if (r < TT) {
                float4 p = *(const float4*)&red[(0 * 128 + cb * 32 + cj) * 4];
                float hn = tanhf(pv + p.x + p.y + p.z + p.w);
                g_h0[nxt][gb][gj] = hn;
                if (r == TT - 1) out[HIDOFF + (size_t)gb * HH + gj] = hn;
            }
        } else if (tid < 256) {
            if (r >= 1) {
                float4 p1 = *(const float4*)&red[(1 * 128 + cb * 32 + cj) * 4];
                float4 p2 = *(const float4*)&red[(2 * 128 + cb * 32 + cj) * 4];
                float hn = tanhf(b1s[cj] + p1.x + p1.y + p1.z + p1.w
                                         + p2.x + p2.y + p2.z + p2.w);
                const int t1 = r - 1;
                g_h1[nxt][gb][gj] = hn;
                out[((size_t)gb * TT + t1) * HH + gj] = hn;
                if (t1 == TT - 1)
                    out[HIDOFF + (size_t)BB * HH + (size_t)gb * HH + gj] = hn;
            }
        }
        if (tid < 128 && r + 1 < TT)
            pv = g_pre[((size_t)(r + 1) * BB + gb) * HH + gj];

        // ---- cluster barrier: release h writes, acquire for next stage ----
        if (r < TT) {
            asm volatile("barrier.cluster.arrive.aligned;" ::: "memory");
            asm volatile("barrier.cluster.wait.aligned;" ::: "memory");
        }
    }
}

// ---------------- launch ----------------------------------------------------
extern "C" void kernel_launch(void* const* d_in, const int* in_sizes, int n_in,
                              void* d_out, int out_size)
{
    (void)in_sizes; (void)n_in; (void)out_size;
    const float* x    = (const float*)d_in[0];
    const float* wih0 = (const float*)d_in[1];
    const float* whh0 = (const float*)d_in[2];
    const float* bih0 = (const float*)d_in[3];
    const float* bhh0 = (const float*)d_in[4];
    const float* wih1 = (const float*)d_in[5];
    const float* whh1 = (const float*)d_in[6];
    const float* bih1 = (const float*)d_in[7];
    const float* bhh1 = (const float*)d_in[8];
    float* out = (float*)d_out;

    cudaFuncSetAttribute(rnn_cluster,
                         cudaFuncAttributeMaxDynamicSharedMemorySize, SMEM_CL);
    cudaFuncSetAttribute(rnn_cluster,
                         cudaFuncAttributeNonPortableClusterSizeAllowed, 1);

    init_state<<<128, 256>>>();

    dim3 gemmGrid(HH / 64, (TT * BB) / 64);   // (8, 512)
    gemm_pre<<<gemmGrid, 256>>>(x, wih0, bih0, bhh0);

    rnn_cluster<<<128, 384, SMEM_CL>>>(whh0, wih1, whh1, bih1, bhh1, out);
}

// round 8
// speedup vs baseline: 1.9450x; 1.9450x over previous
#include <cuda_runtime.h>
#include <math.h>

#define BB 32
#define TT 1024
#define DD 512
#define HH 512
#define HP 516
#define RP 12

// ---------------- scratch (device globals: allocation-free) ----------------
__device__ float g_pre[TT * BB * HH];   // layer-0 input transform + bias, [t][b][j]
__device__ float g_h0[2][BB][HH];       // layer-0 hidden double buffer
__device__ float g_h1[2][BB][HH];       // layer-1 hidden double buffer
__device__ unsigned g_c0[4 * 32];       // per-bg h0 arrival counters (128B apart)
__device__ unsigned g_c1[4 * 32];       // per-bg h1 arrival counters

// ---------------- helpers ----------------------------------------------------
__device__ __forceinline__ unsigned ldacq(const unsigned* p) {
    unsigned v;
    asm volatile("ld.acquire.gpu.u32 %0, [%1];" : "=r"(v) : "l"(p) : "memory");
    return v;
}
__device__ __forceinline__ void red_rel(unsigned* p) {
    asm volatile("red.release.gpu.global.add.u32 [%0], 1;" :: "l"(p) : "memory");
}
__device__ __forceinline__ void fma2(unsigned long long& d,
                                     unsigned long long a, unsigned long long b) {
    asm("fma.rn.f32x2 %0, %1, %2, %0;" : "+l"(d) : "l"(a), "l"(b));
}
#define BARS(id, n) asm volatile("bar.sync %0, %1;" :: "r"(id), "r"(n) : "memory")

// ---------------- init: zero recurrent state + counters ----------------------
__global__ void init_state() {
    int idx = blockIdx.x * blockDim.x + threadIdx.x;
    if (idx < 2 * BB * HH) {
        ((float*)g_h0)[idx] = 0.f;
        ((float*)g_h1)[idx] = 0.f;
    }
    if (idx < 4 * 32) { g_c0[idx] = 0; g_c1[idx] = 0; }
}

// ---------------- pre-GEMM (layer 0 only): pre[t*B+b][j] = x_row.W[j]+bias --
__global__ __launch_bounds__(256) void gemm_pre(
    const float* __restrict__ X, const float* __restrict__ W,
    const float* __restrict__ b1, const float* __restrict__ b2)
{
    __shared__ float As[16][68];
    __shared__ float Bs[16][68];

    const int m0 = blockIdx.y * 64;
    const int n0 = blockIdx.x * 64;
    const int tid = threadIdx.x;
    const int r  = tid >> 2;
    const int kq = tid & 3;
    const int tx = tid & 15;
    const int ty = tid >> 4;

    const int m = m0 + r;
    const int t = m >> 5, b = m & 31;
    const float* arow = X + ((size_t)b * TT + t) * DD;
    const float* brow = W + (size_t)(n0 + r) * DD;

    float acc[4][4];
#pragma unroll
    for (int i = 0; i < 4; i++)
#pragma unroll
        for (int j = 0; j < 4; j++) acc[i][j] = 0.f;

    float4 a_next = *(const float4*)(arow + kq * 4);
    float4 b_next = *(const float4*)(brow + kq * 4);

    for (int kt = 0; kt < DD / 16; kt++) {
        float4 a = a_next, bv = b_next;
        As[kq*4+0][r] = a.x;  As[kq*4+1][r] = a.y;
        As[kq*4+2][r] = a.z;  As[kq*4+3][r] = a.w;
        Bs[kq*4+0][r] = bv.x; Bs[kq*4+1][r] = bv.y;
        Bs[kq*4+2][r] = bv.z; Bs[kq*4+3][r] = bv.w;
        __syncthreads();
        if (kt + 1 < DD / 16) {
            a_next = *(const float4*)(arow + (kt + 1) * 16 + kq * 4);
            b_next = *(const float4*)(brow + (kt + 1) * 16 + kq * 4);
        }
#pragma unroll
        for (int k = 0; k < 16; k++) {
            float4 av = *(const float4*)&As[k][ty * 4];
            float4 bw = *(const float4*)&Bs[k][tx * 4];
            float am[4] = {av.x, av.y, av.z, av.w};
            float bn[4] = {bw.x, bw.y, bw.z, bw.w};
#pragma unroll
            for (int i = 0; i < 4; i++)
#pragma unroll
                for (int j = 0; j < 4; j++) acc[i][j] += am[i] * bn[j];
        }
        __syncthreads();
    }

    float bias[4];
#pragma unroll
    for (int j = 0; j < 4; j++) {
        int n = n0 + tx * 4 + j;
        bias[j] = b1[n] + b2[n];
    }
#pragma unroll
    for (int i = 0; i < 4; i++) {
        int mo = m0 + ty * 4 + i;
        float4 v;
        v.x = acc[i][0] + bias[0];
        v.y = acc[i][1] + bias[1];
        v.z = acc[i][2] + bias[2];
        v.w = acc[i][3] + bias[3];
        *(float4*)&g_pre[(size_t)mo * HH + n0 + tx * 4] = v;
    }
}

// ---------------- warp-specialized fused recurrence --------------------------
// 128 CTAs = 32 j-groups (16 rows) x 4 batch-groups (8 batches). 384 threads.
// G0 (warps 0-3): h0 chain.  G1 (4-7): mat1 + h1 epilogue.  G2 (8-11): mat2.
// Weights permanently in registers (4j x 16k panel per lane).
#define SMEM_WS ((2*8*HP + 8*HP + 3*128*RP + 128*RP + 32) * 4)

__global__ __launch_bounds__(384, 1) void rnn_ws(
    const float* __restrict__ Whh0, const float* __restrict__ Wih1,
    const float* __restrict__ Whh1, const float* __restrict__ bih1,
    const float* __restrict__ bhh1, float* __restrict__ out)
{
    extern __shared__ float sm[];
    float* Hs0  = sm;                    // 2 bufs x 8 x HP
    float* Hs1  = Hs0 + 2 * 8 * HP;      // 8 x HP
    float* red0 = Hs1 + 8 * HP;          // 128 x RP
    float* red1 = red0 + 128 * RP;       // 128 x RP
    float* red2 = red1 + 128 * RP;       // 2 bufs x 128 x RP
    float* b1s  = red2 + 2 * 128 * RP;   // 16

    const int tid  = threadIdx.x;
    const int wid  = tid >> 5;
    const int lane = tid & 31;
    const int bg = blockIdx.x >> 5;      // 0..3
    const int jg = blockIdx.x & 31;      // 0..31

    const int grp = wid >> 2;            // 0,1,2
    const int w4  = wid & 3;             // warp within group
    const int jq  = lane & 3;
    const int ksl = lane >> 2;           // 0..7
    const int ks  = w4 * 8 + ksl;        // 0..31 k-slice (16 floats)

    // ---- W panel into registers: rows jg*16 + jq*4 + jj, k in [ks*16,+16) ----
    const float* Wsrc = (grp == 0) ? Whh0 : (grp == 1) ? Wih1 : Whh1;
    unsigned long long wreg[4][8];
#pragma unroll
    for (int jj = 0; jj < 4; jj++) {
        const float* wr = Wsrc + (size_t)(jg * 16 + jq * 4 + jj) * HH + ks * 16;
#pragma unroll
        for (int c = 0; c < 8; c++)
            wreg[jj][c] = *(const unsigned long long*)(wr + c * 2);
    }

    // ---- prezero smem tiles / load bias ----
    if (grp == 0) {
        for (int i = tid; i < 2 * 8 * HP; i += 128) Hs0[i] = 0.f;
    } else if (grp == 2) {
        for (int i = tid - 256; i < 8 * HP; i += 128) Hs1[i] = 0.f;
    } else {
        if (tid - 128 < 16) {
            int j = tid - 128;
            b1s[j] = bih1[jg * 16 + j] + bhh1[jg * 16 + j];
        }
    }
    __syncthreads();

    unsigned* cnt0 = &g_c0[bg * 32];
    unsigned* cnt1 = &g_c1[bg * 32];

    const int crow = tid & 127;          // consumer row 0..127
    const int eb = crow >> 4, ej = crow & 15;
    const int gb = bg * 8 + eb;
    const int gj = jg * 16 + ej;
    const size_t HIDOFF = (size_t)BB * TT * HH;

    // =========================== G0: h0 chain ===============================
    if (grp == 0) {
        float pv = g_pre[((size_t)0 * BB + gb) * HH + gj];
        for (int r = 0; r <= TT; r++) {
            float* Hb = Hs0 + (r & 1) * 8 * HP;
            if (r > 0) {
                if (lane == 0) { while (ldacq(cnt0) < (unsigned)(32 * r)) { } }
                __syncwarp();
                // stage h0[r-1]
#pragma unroll
                for (int it = 0; it < 8; it++) {
                    int idx = it * 128 + tid;
                    int b = idx >> 7, c = idx & 127;
                    int ph = c ^ ((c >> 2) & 7);
                    *(float4*)&Hb[b * HP + ph * 4] =
                        *(const float4*)&g_h0[(r - 1) & 1][bg * 8 + b][c * 4];
                }
            }
            BARS(1, 256);                 // Hs0 ready (G0+G1)

            if (r < TT) {
                unsigned long long acc[4][8];
#pragma unroll
                for (int a = 0; a < 4; a++)
#pragma unroll
                    for (int b = 0; b < 8; b++) acc[a][b] = 0ull;
#pragma unroll
                for (int i = 0; i < 4; i++) {
                    int ph = (ks * 4 + i) ^ ksl;
#pragma unroll
                    for (int b = 0; b < 8; b++) {
                        ulonglong2 h2 = *(const ulonglong2*)&Hb[b * HP + ph * 4];
#pragma unroll
                        for (int jj = 0; jj < 4; jj++) {
                            fma2(acc[jj][b], wreg[jj][2 * i],     h2.x);
                            fma2(acc[jj][b], wreg[jj][2 * i + 1], h2.y);
                        }
                    }
                }
                float part[4][8];
#pragma unroll
                for (int jj = 0; jj < 4; jj++)
#pragma unroll
                    for (int b = 0; b < 8; b++) {
                        unsigned long long v = acc[jj][b];
                        part[jj][b] = __uint_as_float((unsigned)v)
                                    + __uint_as_float((unsigned)(v >> 32));
                    }
#pragma unroll
                for (int m = 4; m <= 16; m <<= 1)
#pragma unroll
                    for (int jj = 0; jj < 4; jj++)
#pragma unroll
                        for (int b = 0; b < 8; b++)
                            part[jj][b] += __shfl_xor_sync(0xffffffffu, part[jj][b], m);
                if (ksl == 0) {
#pragma unroll
                    for (int jj = 0; jj < 4; jj++)
#pragma unroll
                        for (int b = 0; b < 8; b++)
                            red0[(b * 16 + jq * 4 + jj) * RP + w4] = part[jj][b];
                }
            }
            BARS(2, 128);                 // red0 ready (G0)
            if (r < TT) {
                float4 p = *(const float4*)&red0[crow * RP];
                float hn = tanhf(pv + p.x + p.y + p.z + p.w);
                g_h0[r & 1][gb][gj] = hn;
                if (r == TT - 1) out[HIDOFF + (size_t)gb * HH + gj] = hn;
                if (r + 1 < TT) pv = g_pre[((size_t)(r + 1) * BB + gb) * HH + gj];
            }
            BARS(3, 128);                 // h0 stores done (G0)
            if (r < TT && tid == 0) red_rel(cnt0);
        }
    }
    // =========================== G1: mat1 + h1 ==============================
    else if (grp == 1) {
        for (int r = 0; r <= TT; r++) {
            float* Hb = Hs0 + (r & 1) * 8 * HP;
            BARS(1, 256);                 // wait Hs0 staged by G0

            unsigned long long acc[4][8];
#pragma unroll
            for (int a = 0; a < 4; a++)
#pragma unroll
                for (int b = 0; b < 8; b++) acc[a][b] = 0ull;
#pragma unroll
            for (int i = 0; i < 4; i++) {
                int ph = (ks * 4 + i) ^ ksl;
#pragma unroll
                for (int b = 0; b < 8; b++) {
                    ulonglong2 h2 = *(const ulonglong2*)&Hb[b * HP + ph * 4];
#pragma unroll
                    for (int jj = 0; jj < 4; jj++) {
                        fma2(acc[jj][b], wreg[jj][2 * i],     h2.x);
                        fma2(acc[jj][b], wreg[jj][2 * i + 1], h2.y);
                    }
                }
            }
            float part[4][8];
#pragma unroll
            for (int jj = 0; jj < 4; jj++)
#pragma unroll
                for (int b = 0; b < 8; b++) {
                    unsigned long long v = acc[jj][b];
                    part[jj][b] = __uint_as_float((unsigned)v)
                                + __uint_as_float((unsigned)(v >> 32));
                }
#pragma unroll
            for (int m = 4; m <= 16; m <<= 1)
#pragma unroll
                for (int jj = 0; jj < 4; jj++)
#pragma unroll
                    for (int b = 0; b < 8; b++)
                        part[jj][b] += __shfl_xor_sync(0xffffffffu, part[jj][b], m);
            if (ksl == 0) {
#pragma unroll
                for (int jj = 0; jj < 4; jj++)
#pragma unroll
                    for (int b = 0; b < 8; b++)
                        red1[(b * 16 + jq * 4 + jj) * RP + w4] = part[jj][b];
            }
            BARS(4, 256);                 // red1 + red2 ready (G1+G2)
            if (r >= 1) {
                const int t1 = r - 1;
                float4 p1 = *(const float4*)&red1[crow * RP];
                float4 p2 = *(const float4*)&red2[(r & 1) * 128 * RP + crow * RP];
                float hn = tanhf(b1s[ej] + p1.x + p1.y + p1.z + p1.w
                                         + p2.x + p2.y + p2.z + p2.w);
                g_h1[t1 & 1][gb][gj] = hn;
                out[((size_t)gb * TT + t1) * HH + gj] = hn;
                if (t1 == TT - 1)
                    out[HIDOFF + (size_t)BB * HH + (size_t)gb * HH + gj] = hn;
            }
            BARS(5, 128);                 // h1 stores done (G1)
            if (r >= 1 && r < TT && tid == 128) red_rel(cnt1);
        }
    }
    // =========================== G2: mat2 ===================================
    else {
        const int ltid = tid - 256;
        for (int r = 0; r <= TT; r++) {
            if (r >= 2) {
                if (lane == 0) { while (ldacq(cnt1) < (unsigned)(32 * (r - 1))) { } }
                __syncwarp();
                // stage h1[r-2]
#pragma unroll
                for (int it = 0; it < 8; it++) {
                    int idx = it * 128 + ltid;
                    int b = idx >> 7, c = idx & 127;
                    int ph = c ^ ((c >> 2) & 7);
                    *(float4*)&Hs1[b * HP + ph * 4] =
                        *(const float4*)&g_h1[(r - 2) & 1][bg * 8 + b][c * 4];
                }
            }
            BARS(6, 128);                 // Hs1 ready (G2)

            unsigned long long acc[4][8];
#pragma unroll
            for (int a = 0; a < 4; a++)
#pragma unroll
                for (int b = 0; b < 8; b++) acc[a][b] = 0ull;
#pragma unroll
            for (int i = 0; i < 4; i++) {
                int ph = (ks * 4 + i) ^ ksl;
#pragma unroll
                for (int b = 0; b < 8; b++) {
                    ulonglong2 h2 = *(const ulonglong2*)&Hs1[b * HP + ph * 4];
#pragma unroll
                    for (int jj = 0; jj < 4; jj++) {
                        fma2(acc[jj][b], wreg[jj][2 * i],     h2.x);
                        fma2(acc[jj][b], wreg[jj][2 * i + 1], h2.y);
                    }
                }
            }
            float part[4][8];
#pragma unroll
            for (int jj = 0; jj < 4; jj++)
#pragma unroll
                for (int b = 0; b < 8; b++) {
                    unsigned long long v = acc[jj][b];
                    part[jj][b] = __uint_as_float((unsigned)v)
                                + __uint_as_float((unsigned)(v >> 32));
                }
#pragma unroll
            for (int m = 4; m <= 16; m <<= 1)
#pragma unroll
                for (int jj = 0; jj < 4; jj++)
#pragma unroll
                    for (int b = 0; b < 8; b++)
                        part[jj][b] += __shfl_xor_sync(0xffffffffu, part[jj][b], m);
            if (ksl == 0) {
#pragma unroll
                for (int jj = 0; jj < 4; jj++)
#pragma unroll
                    for (int b = 0; b < 8; b++)
                        red2[(r & 1) * 128 * RP + (b * 16 + jq * 4 + jj) * RP + w4]
                            = part[jj][b];
            }
            BARS(4, 256);                 // join G1
        }
    }
}

// ---------------- launch ----------------------------------------------------
extern "C" void kernel_launch(void* const* d_in, const int* in_sizes, int n_in,
                              void* d_out, int out_size)
{
    (void)in_sizes; (void)n_in; (void)out_size;
    const float* x    = (const float*)d_in[0];
    const float* wih0 = (const float*)d_in[1];
    const float* whh0 = (const float*)d_in[2];
    const float* bih0 = (const float*)d_in[3];
    const float* bhh0 = (const float*)d_in[4];
    const float* wih1 = (const float*)d_in[5];
    const float* whh1 = (const float*)d_in[6];
    const float* bih1 = (const float*)d_in[7];
    const float* bhh1 = (const float*)d_in[8];
    float* out = (float*)d_out;

    cudaFuncSetAttribute(rnn_ws,
                         cudaFuncAttributeMaxDynamicSharedMemorySize, SMEM_WS);

    init_state<<<128, 256>>>();

    dim3 gemmGrid(HH / 64, (TT * BB) / 64);   // (8, 512)
    gemm_pre<<<gemmGrid, 256>>>(x, wih0, bih0, bhh0);

    rnn_ws<<<128, 384, SMEM_WS>>>(whh0, wih1, whh1, bih1, bhh1, out);
}